// round 10
// baseline (speedup 1.0000x reference)
#include <cuda_runtime.h>
#include <cuda_bf16.h>
#include <cstdint>

typedef unsigned long long ull;
typedef unsigned short u16;
typedef unsigned int u32;

// ---------------- Problem constants ----------------
#define A_DIM 512
#define V_DIM 768
#define L_DIM 1024
#define H_DIM 512
#define BB    16
#define SS    2048
#define ROWS  (BB * SS)        // 32768
#define G4    (4 * H_DIM)      // 2048
#define CAT_K 1536

// ---------------- Scratch (device globals; no allocation allowed) ----------------
__device__ float g_cat[(size_t)ROWS * CAT_K];
__device__ float g_ctx[(size_t)ROWS * H_DIM];
__device__ float g_xg [(size_t)ROWS * G4];
__device__ float g_hbuf[2 * BB * H_DIM];
__device__ float g_bsum[G4];
#define FLAG_STRIDE 8
__device__ unsigned g_flags[128 * FLAG_STRIDE];   // per-CTA step flags (32B apart)

__device__ __align__(16) u16 g_ahi[(size_t)ROWS * A_DIM],  g_alo[(size_t)ROWS * A_DIM];
__device__ __align__(16) u16 g_vhi[(size_t)ROWS * V_DIM],  g_vlo[(size_t)ROWS * V_DIM];
__device__ __align__(16) u16 g_lhi[(size_t)ROWS * L_DIM],  g_llo[(size_t)ROWS * L_DIM];
__device__ __align__(16) u16 g_cathi[(size_t)ROWS * CAT_K], g_catlo[(size_t)ROWS * CAT_K];
__device__ __align__(16) u16 g_fushi[(size_t)ROWS * H_DIM], g_fuslo[(size_t)ROWS * H_DIM];
__device__ __align__(16) u16 g_wahi[H_DIM * A_DIM],  g_walo[H_DIM * A_DIM];
__device__ __align__(16) u16 g_wvhi[H_DIM * V_DIM],  g_wvlo[H_DIM * V_DIM];
__device__ __align__(16) u16 g_wlhi[H_DIM * L_DIM],  g_wllo[H_DIM * L_DIM];
__device__ __align__(16) u16 g_wchi[H_DIM * CAT_K],  g_wclo[H_DIM * CAT_K];
__device__ __align__(16) u16 g_wihhi[G4 * H_DIM],    g_wihlo[G4 * H_DIM];

// ---------------- helpers ----------------
__device__ __forceinline__ ull ffma2(ull a, ull b, ull c) {
    asm("fma.rn.f32x2 %0, %1, %2, %0;" : "+l"(c) : "l"(a), "l"(b));
    return c;
}
__device__ __forceinline__ void unpack2(ull v, float& x, float& y) {
    asm("mov.b64 {%0, %1}, %2;" : "=f"(x), "=f"(y) : "l"(v));
}
__device__ __forceinline__ float sigmf(float x) { return 1.0f / (1.0f + __expf(-x)); }

__device__ __forceinline__ u32 smem_u32(const void* p) {
    u32 a;
    asm("{ .reg .u64 t; cvta.to.shared.u64 t, %1; cvt.u32.u64 %0, t; }" : "=r"(a) : "l"(p));
    return a;
}

#define SWZ128(x) ((x) ^ (((x) >> 3) & 0x70))

__device__ __forceinline__ void ldsm4(u32& r0, u32& r1, u32& r2, u32& r3, u32 addr) {
    asm volatile("ldmatrix.sync.aligned.m8n8.x4.shared.b16 {%0,%1,%2,%3}, [%4];"
        : "=r"(r0), "=r"(r1), "=r"(r2), "=r"(r3) : "r"(addr));
}
__device__ __forceinline__ void mma16816(float* c, const u32* a, u32 b0, u32 b1) {
    asm volatile("mma.sync.aligned.m16n8k16.row.col.f32.bf16.bf16.f32 "
        "{%0,%1,%2,%3}, {%4,%5,%6,%7}, {%8,%9}, {%0,%1,%2,%3};"
        : "+f"(c[0]), "+f"(c[1]), "+f"(c[2]), "+f"(c[3])
        : "r"(a[0]), "r"(a[1]), "r"(a[2]), "r"(a[3]), "r"(b0), "r"(b1));
}
__device__ __forceinline__ void cp16(u32 saddr, const void* g) {
    asm volatile("cp.async.cg.shared.global [%0], [%1], 16;" :: "r"(saddr), "l"(g));
}

// ---------------- Init ----------------
__global__ void init_kernel(const float* __restrict__ bih, const float* __restrict__ bhh) {
    int i = blockIdx.x * blockDim.x + threadIdx.x;
    if (i < G4) g_bsum[i] = bih[i] + bhh[i];
    if (i < 128 * FLAG_STRIDE) g_flags[i] = 0u;
}

// ---------------- fp32 -> bf16 hi/lo splits (fused, vectorized) ----------------
__device__ __forceinline__ void split4(const float* __restrict__ s, u16* __restrict__ hi,
                                       u16* __restrict__ lo, size_t i) {
    float4 x = ((const float4*)s)[i];
    float xs[4] = { x.x, x.y, x.z, x.w };
    u32 hp[2], lp[2];
#pragma unroll
    for (int q = 0; q < 2; q++) {
        __nv_bfloat16 h0 = __float2bfloat16(xs[2 * q]);
        __nv_bfloat16 h1 = __float2bfloat16(xs[2 * q + 1]);
        float r0 = xs[2 * q]     - __bfloat162float(h0);
        float r1 = xs[2 * q + 1] - __bfloat162float(h1);
        __nv_bfloat16 l0 = __float2bfloat16(r0);
        __nv_bfloat16 l1 = __float2bfloat16(r1);
        hp[q] = (u32)*(u16*)&h0 | ((u32)*(u16*)&h1 << 16);
        lp[q] = (u32)*(u16*)&l0 | ((u32)*(u16*)&l1 << 16);
    }
    ((uint2*)hi)[i] = make_uint2(hp[0], hp[1]);
    ((uint2*)lo)[i] = make_uint2(lp[0], lp[1]);
}

__global__ void split_in_kernel(const float* __restrict__ a, const float* __restrict__ v,
                                const float* __restrict__ l) {
    const size_t i = (size_t)blockIdx.x * blockDim.x + threadIdx.x;
    const int seg = blockIdx.y;
    if (seg == 0) { if (i < (size_t)ROWS * A_DIM / 4) split4(a, g_ahi, g_alo, i); }
    else if (seg == 1) { if (i < (size_t)ROWS * V_DIM / 4) split4(v, g_vhi, g_vlo, i); }
    else { split4(l, g_lhi, g_llo, i); }
}

__global__ void split_w_kernel(const float* __restrict__ wa, const float* __restrict__ wv,
                               const float* __restrict__ wl, const float* __restrict__ wc,
                               const float* __restrict__ wih) {
    const size_t i = (size_t)blockIdx.x * blockDim.x + threadIdx.x;
    const int seg = blockIdx.y;
    if (seg == 0)      { if (i < (size_t)H_DIM * A_DIM / 4) split4(wa, g_wahi, g_walo, i); }
    else if (seg == 1) { if (i < (size_t)H_DIM * V_DIM / 4) split4(wv, g_wvhi, g_wvlo, i); }
    else if (seg == 2) { if (i < (size_t)H_DIM * L_DIM / 4) split4(wl, g_wlhi, g_wllo, i); }
    else if (seg == 3) { if (i < (size_t)H_DIM * CAT_K / 4) split4(wc, g_wchi, g_wclo, i); }
    else               { split4(wih, g_wihhi, g_wihlo, i); }
}

// ---------------- merged-pass pipelined mma.sync GEMM (unchanged from R9) ----------------
#define STAGES 3
#define TILE_B 16384
#define STG_BYTES (4 * TILE_B)
#define GSMEM_BYTES (STAGES * STG_BYTES)

template<int MODE>
__global__ __launch_bounds__(256, 1)
void mma_gemm(const u16* __restrict__ Xhi, const u16* __restrict__ Xlo,
              const u16* __restrict__ Whi, const u16* __restrict__ Wlo,
              const float* __restrict__ bias, float* __restrict__ Cf,
              u16* __restrict__ Chi, u16* __restrict__ Clo,
              int K, int ldc)
{
    extern __shared__ __align__(16) char smem[];
    const u32 sbase = smem_u32(smem);

    const int tid  = threadIdx.x;
    const int lane = tid & 31;
    const int w    = tid >> 5;
    const int wm   = w & 3;
    const int wn   = w >> 2;
    const int m0 = blockIdx.y * 128;
    const int n0 = blockIdx.x * 128;

    float acc[2][8][4];
#pragma unroll
    for (int i = 0; i < 2; i++)
#pragma unroll
        for (int j = 0; j < 8; j++)
#pragma unroll
            for (int q = 0; q < 4; q++) acc[i][j][q] = 0.f;

    const int a_row = wm * 32 + (lane & 15);
    const int a_kb  = (lane >> 4) * 16;
    const int b_row = wn * 64 + (lane & 7) + ((lane >> 4) << 3);
    const int b_kb  = ((lane >> 3) & 1) * 16;

    const int KP = K / 64;

    auto issue = [&](int ch) {
        if (ch < KP) {
            const int kk = ch;
            const u16* A0 = Xhi + (size_t)m0 * K + kk * 64;
            const u16* A1 = Xlo + (size_t)m0 * K + kk * 64;
            const u16* B0 = Whi + (size_t)n0 * K + kk * 64;
            const u16* B1 = Wlo + (size_t)n0 * K + kk * 64;
            const u32 st = sbase + (ch % STAGES) * STG_BYTES;
#pragma unroll
            for (int i = 0; i < 4; i++) {
                const int id  = tid + 256 * i;
                const int row = id >> 3;
                const int c   = id & 7;
                const u32 off = SWZ128(row * 128 + c * 16);
                const size_t g = (size_t)row * K + c * 8;
                cp16(st + 0 * TILE_B + off, A0 + g);
                cp16(st + 1 * TILE_B + off, A1 + g);
                cp16(st + 2 * TILE_B + off, B0 + g);
                cp16(st + 3 * TILE_B + off, B1 + g);
            }
        }
        asm volatile("cp.async.commit_group;");
    };

    issue(0);
    issue(1);

    for (int ch = 0; ch < KP; ch++) {
        asm volatile("cp.async.wait_group 1;");
        __syncthreads();
        issue(ch + 2);

        const u32 st = sbase + (ch % STAGES) * STG_BYTES;
        const u32 sAh = st, sAl = st + TILE_B, sBh = st + 2 * TILE_B, sBl = st + 3 * TILE_B;

#pragma unroll
        for (int ks = 0; ks < 4; ks++) {
            const int kb = ks * 32;
            u32 ah[2][4], al[2][4];
#pragma unroll
            for (int mt = 0; mt < 2; mt++) {
                const u32 ao = SWZ128((a_row + mt * 16) * 128 + a_kb + kb);
                ldsm4(ah[mt][0], ah[mt][1], ah[mt][2], ah[mt][3], sAh + ao);
                ldsm4(al[mt][0], al[mt][1], al[mt][2], al[mt][3], sAl + ao);
            }
#pragma unroll
            for (int nt = 0; nt < 4; nt++) {
                const u32 bo = SWZ128((b_row + nt * 16) * 128 + b_kb + kb);
                u32 bh0, bh1, bh2, bh3, bl0, bl1, bl2, bl3;
                ldsm4(bh0, bh1, bh2, bh3, sBh + bo);
                ldsm4(bl0, bl1, bl2, bl3, sBl + bo);
#pragma unroll
                for (int mt = 0; mt < 2; mt++) {
                    mma16816(acc[mt][2 * nt],     ah[mt], bh0, bh1);
                    mma16816(acc[mt][2 * nt + 1], ah[mt], bh2, bh3);
                    mma16816(acc[mt][2 * nt],     ah[mt], bl0, bl1);
                    mma16816(acc[mt][2 * nt + 1], ah[mt], bl2, bl3);
                    mma16816(acc[mt][2 * nt],     al[mt], bh0, bh1);
                    mma16816(acc[mt][2 * nt + 1], al[mt], bh2, bh3);
                }
            }
        }
    }

    const int mb = m0 + wm * 32 + (lane >> 2);
    const int nb = n0 + wn * 64 + (lane & 3) * 2;
#pragma unroll
    for (int mt = 0; mt < 2; mt++) {
#pragma unroll
        for (int nt = 0; nt < 8; nt++) {
            const int n = nb + nt * 8;
            const float b0 = bias[n], b1 = bias[n + 1];
#pragma unroll
            for (int h = 0; h < 2; h++) {
                const int m = mb + mt * 16 + h * 8;
                float v0 = acc[mt][nt][2 * h]     + b0;
                float v1 = acc[mt][nt][2 * h + 1] + b1;
                if (MODE == 1) { v0 = tanhf(v0); v1 = tanhf(v1); }
                *(float2*)&Cf[(size_t)m * ldc + n] = make_float2(v0, v1);
                if (MODE == 0) {
                    __nv_bfloat16 h0 = __float2bfloat16(v0);
                    __nv_bfloat16 h1 = __float2bfloat16(v1);
                    float r0 = v0 - __bfloat162float(h0);
                    float r1 = v1 - __bfloat162float(h1);
                    __nv_bfloat16 l0 = __float2bfloat16(r0);
                    __nv_bfloat16 l1 = __float2bfloat16(r1);
                    u32 hp = (u32)*(u16*)&h0 | ((u32)*(u16*)&h1 << 16);
                    u32 lp = (u32)*(u16*)&l0 | ((u32)*(u16*)&l1 << 16);
                    *(u32*)&Chi[(size_t)m * ldc + n] = hp;
                    *(u32*)&Clo[(size_t)m * ldc + n] = lp;
                }
            }
        }
    }
}

// ---------------- Attention fusion -> bf16 hi/lo fusion ----------------
__global__ __launch_bounds__(256)
void fusion_kernel()
{
    const int warp = threadIdx.x >> 5;
    const int lane = threadIdx.x & 31;
    const int row  = blockIdx.x * 8 + warp;

    const float* crow = g_cat + (size_t)row * CAT_K;
    const float* xrow = g_ctx + (size_t)row * H_DIM;

    float av[16], vv[16], lv[16];
    float sa = 0.f, sv = 0.f, sl = 0.f;
#pragma unroll
    for (int q = 0; q < 16; q++) {
        const int k = lane + 32 * q;
        const float c = xrow[k];
        av[q] = crow[k];
        vv[q] = crow[512 + k];
        lv[q] = crow[1024 + k];
        sa = fmaf(av[q], c, sa);
        sv = fmaf(vv[q], c, sv);
        sl = fmaf(lv[q], c, sl);
    }
#pragma unroll
    for (int m = 16; m >= 1; m >>= 1) {
        sa += __shfl_xor_sync(0xffffffffu, sa, m);
        sv += __shfl_xor_sync(0xffffffffu, sv, m);
        sl += __shfl_xor_sync(0xffffffffu, sl, m);
    }
    const float mx = fmaxf(sa, fmaxf(sv, sl));
    const float ea = __expf(sa - mx);
    const float ev = __expf(sv - mx);
    const float el = __expf(sl - mx);
    const float inv = 1.0f / (ea + ev + el);
    const float wa = ea * inv, wv = ev * inv, wl = el * inv;

    u16* fh = g_fushi + (size_t)row * H_DIM;
    u16* fl = g_fuslo + (size_t)row * H_DIM;
#pragma unroll
    for (int q = 0; q < 16; q++) {
        const int k = lane + 32 * q;
        const float v = wa * av[q] + wv * vv[q] + wl * lv[q];
        __nv_bfloat16 h = __float2bfloat16(v);
        float rr = v - __bfloat162float(h);
        __nv_bfloat16 l = __float2bfloat16(rr);
        fh[k] = *(u16*)&h;
        fl[k] = *(u16*)&l;
    }
}

// ---------------- Persistent LSTM: flag barrier + 9-shfl reduction ----------------
#define NCTA 128
#define OFF_R ((size_t)BB * SS * H_DIM)

__global__ __launch_bounds__(256, 1)
void lstm_kernel(const float* __restrict__ h0, const float* __restrict__ c0,
                 const float* __restrict__ Whh, float* __restrict__ out)
{
    __shared__ __align__(16) float h_s[BB * H_DIM];
    __shared__ float gates_s[4][4][BB];

    const int tid   = threadIdx.x;
    const int w     = tid >> 5;
    const int lane  = tid & 31;
    const int c     = blockIdx.x;
    const int gpair = w >> 2;
    const int bq    = w & 3;

    ull wgt[8][8];
#pragma unroll
    for (int r = 0; r < 8; r++) {
        const int gate = 2 * gpair + (r >> 2);
        const int j    = r & 3;
        const float* wr = Whh + (size_t)(gate * H_DIM + 4 * c + j) * H_DIM;
#pragma unroll
        for (int ic = 0; ic < 4; ic++) {
            ulonglong2 u = *(const ulonglong2*)(wr + 4 * lane + 128 * ic);
            wgt[r][2 * ic]     = u.x;
            wgt[r][2 * ic + 1] = u.y;
        }
    }

    const int jn = tid >> 4;
    const int b  = tid & 15;
    float c_val = 0.f;
    if (tid < 64) c_val = c0[b * H_DIM + 4 * c + jn];

    unsigned* myflag = &g_flags[c * FLAG_STRIDE];
    unsigned* pollflag = (tid < NCTA) ? &g_flags[tid * FLAG_STRIDE] : &g_flags[0];

    for (int t = 0; t < SS; t++) {
        // prefetch xg for this step (independent of the recurrence)
        float xv0 = 0.f, xv1 = 0.f, xv2 = 0.f, xv3 = 0.f;
        if (tid < 64) {
            const float* xr = g_xg + ((size_t)(b * SS + t)) * G4 + 4 * c + jn;
            xv0 = xr[0 * H_DIM];
            xv1 = xr[1 * H_DIM];
            xv2 = xr[2 * H_DIM];
            xv3 = xr[3 * H_DIM];
        }

        // wait for all CTAs to publish h_{t-1} (flag value == t)
        if (t > 0) {
            const unsigned target = (unsigned)t;
            for (;;) {
                unsigned f = target;
                if (tid < NCTA)
                    asm volatile("ld.acquire.gpu.u32 %0, [%1];" : "=r"(f) : "l"(pollflag));
                if (__syncthreads_and((int)(f >= target))) break;
            }
        }

        // stage h_{t-1} into smem
        {
            const float* hsrc = (t == 0) ? h0 : (g_hbuf + (size_t)(t & 1) * (BB * H_DIM));
#pragma unroll
            for (int q = 0; q < 8; q++)
                ((float4*)h_s)[tid + 256 * q] = ((const float4*)hsrc)[tid + 256 * q];
        }
        __syncthreads();

        // gate partials: (8 rows) . h[bb] for 4 batches, 9-shfl butterfly reduction
#pragma unroll
        for (int bi = 0; bi < 4; bi++) {
            const int bb = 4 * bq + bi;
            ull hv[8];
#pragma unroll
            for (int ic = 0; ic < 4; ic++) {
                ulonglong2 u = *(const ulonglong2*)&h_s[bb * H_DIM + 4 * lane + 128 * ic];
                hv[2 * ic]     = u.x;
                hv[2 * ic + 1] = u.y;
            }
            ull acc[8];
#pragma unroll
            for (int r = 0; r < 8; r++) acc[r] = 0ull;
#pragma unroll
            for (int kq = 0; kq < 8; kq++)
#pragma unroll
                for (int r = 0; r < 8; r++)
                    acc[r] = ffma2(wgt[r][kq], hv[kq], acc[r]);

            float v[8];
#pragma unroll
            for (int r = 0; r < 8; r++) {
                float x, y;
                unpack2(acc[r], x, y);
                v[r] = x + y;
            }
            // butterfly: fold rows across lanes (9 shuffles for 8 row-sums)
#pragma unroll
            for (int i = 0; i < 4; i++) {
                float send = (lane & 16) ? v[i] : v[i + 4];
                float recv = __shfl_xor_sync(0xffffffffu, send, 16);
                v[i] = ((lane & 16) ? v[i + 4] : v[i]) + recv;
            }
#pragma unroll
            for (int i = 0; i < 2; i++) {
                float send = (lane & 8) ? v[i] : v[i + 2];
                float recv = __shfl_xor_sync(0xffffffffu, send, 8);
                v[i] = ((lane & 8) ? v[i + 2] : v[i]) + recv;
            }
            {
                float send = (lane & 4) ? v[0] : v[1];
                float recv = __shfl_xor_sync(0xffffffffu, send, 4);
                v[0] = ((lane & 4) ? v[1] : v[0]) + recv;
            }
            v[0] += __shfl_xor_sync(0xffffffffu, v[0], 2);
            v[0] += __shfl_xor_sync(0xffffffffu, v[0], 1);
            const int row = ((lane >> 4) & 1) * 4 + ((lane >> 3) & 1) * 2 + ((lane >> 2) & 1);
            if ((lane & 3) == 0)
                gates_s[2 * gpair + (row >> 2)][row & 3][bb] = v[0];
        }
        __syncthreads();

        // gate combine + state update + write h
        if (tid < 64) {
            const float gi = gates_s[0][jn][b] + xv0;
            const float gf = gates_s[1][jn][b] + xv1;
            const float gg = gates_s[2][jn][b] + xv2;
            const float go = gates_s[3][jn][b] + xv3;
            const float iv = sigmf(gi);
            const float fv = sigmf(gf);
            const float gv = tanhf(gg);
            const float ov = sigmf(go);
            c_val = fv * c_val + iv * gv;
            const float h = ov * tanhf(c_val);
            const int col = 4 * c + jn;
            g_hbuf[(size_t)((t + 1) & 1) * (BB * H_DIM) + b * H_DIM + col] = h;
            out[((size_t)(b * SS + t)) * H_DIM + col] = h;
            if (t == SS - 1) {
                out[OFF_R + b * H_DIM + col]              = h;
                out[OFF_R + BB * H_DIM + b * H_DIM + col] = c_val;
            }
        }
        __threadfence();
        __syncthreads();
        if (tid == 0) {
            const unsigned nf = (unsigned)(t + 1);
            asm volatile("st.release.gpu.u32 [%0], %1;" :: "l"(myflag), "r"(nf) : "memory");
        }
    }
}

// ---------------- Launch ----------------
extern "C" void kernel_launch(void* const* d_in, const int* in_sizes, int n_in,
                              void* d_out, int out_size)
{
    const float* a_in = (const float*)d_in[0];
    const float* v_in = (const float*)d_in[1];
    const float* l_in = (const float*)d_in[2];
    const float* h0   = (const float*)d_in[3];
    const float* c0   = (const float*)d_in[4];
    const float* Wa   = (const float*)d_in[5];
    const float* ba   = (const float*)d_in[6];
    const float* Wv   = (const float*)d_in[7];
    const float* bv   = (const float*)d_in[8];
    const float* Wl   = (const float*)d_in[9];
    const float* bl   = (const float*)d_in[10];
    const float* Wc   = (const float*)d_in[11];
    const float* bc   = (const float*)d_in[12];
    const float* Wih  = (const float*)d_in[13];
    const float* Whh  = (const float*)d_in[14];
    const float* bih  = (const float*)d_in[15];
    const float* bhh  = (const float*)d_in[16];
    float* out = (float*)d_out;

    float *cat, *ctx, *xg, *bsum;
    cudaGetSymbolAddress((void**)&cat,  g_cat);
    cudaGetSymbolAddress((void**)&ctx,  g_ctx);
    cudaGetSymbolAddress((void**)&xg,   g_xg);
    cudaGetSymbolAddress((void**)&bsum, g_bsum);
    u16 *ahi,*alo,*vhi,*vlo,*lhi,*llo,*cathi,*catlo,*fushi,*fuslo;
    u16 *wahi,*walo,*wvhi,*wvlo,*wlhi,*wllo,*wchi,*wclo,*wihhi,*wihlo;
    cudaGetSymbolAddress((void**)&ahi, g_ahi);   cudaGetSymbolAddress((void**)&alo, g_alo);
    cudaGetSymbolAddress((void**)&vhi, g_vhi);   cudaGetSymbolAddress((void**)&vlo, g_vlo);
    cudaGetSymbolAddress((void**)&lhi, g_lhi);   cudaGetSymbolAddress((void**)&llo, g_llo);
    cudaGetSymbolAddress((void**)&cathi, g_cathi); cudaGetSymbolAddress((void**)&catlo, g_catlo);
    cudaGetSymbolAddress((void**)&fushi, g_fushi); cudaGetSymbolAddress((void**)&fuslo, g_fuslo);
    cudaGetSymbolAddress((void**)&wahi, g_wahi); cudaGetSymbolAddress((void**)&walo, g_walo);
    cudaGetSymbolAddress((void**)&wvhi, g_wvhi); cudaGetSymbolAddress((void**)&wvlo, g_wvlo);
    cudaGetSymbolAddress((void**)&wlhi, g_wlhi); cudaGetSymbolAddress((void**)&wllo, g_wllo);
    cudaGetSymbolAddress((void**)&wchi, g_wchi); cudaGetSymbolAddress((void**)&wclo, g_wclo);
    cudaGetSymbolAddress((void**)&wihhi, g_wihhi); cudaGetSymbolAddress((void**)&wihlo, g_wihlo);

    cudaFuncSetAttribute(mma_gemm<0>, cudaFuncAttributeMaxDynamicSharedMemorySize, GSMEM_BYTES);
    cudaFuncSetAttribute(mma_gemm<1>, cudaFuncAttributeMaxDynamicSharedMemorySize, GSMEM_BYTES);
    cudaFuncSetAttribute(mma_gemm<2>, cudaFuncAttributeMaxDynamicSharedMemorySize, GSMEM_BYTES);

    init_kernel<<<2, 1024>>>(bih, bhh);
    split_in_kernel<<<dim3(32768, 3), 256>>>(a_in, v_in, l_in);
    split_w_kernel<<<dim3(1024, 5), 256>>>(Wa, Wv, Wl, Wc, Wih);

    // projections -> cat fp32 + cat hi/lo (row stride 1536)
    mma_gemm<0><<<dim3(4, 256), 256, GSMEM_BYTES>>>(ahi, alo, wahi, walo, ba,
        cat,        cathi,        catlo,        A_DIM, CAT_K);
    mma_gemm<0><<<dim3(4, 256), 256, GSMEM_BYTES>>>(vhi, vlo, wvhi, wvlo, bv,
        cat + 512,  cathi + 512,  catlo + 512,  V_DIM, CAT_K);
    mma_gemm<0><<<dim3(4, 256), 256, GSMEM_BYTES>>>(lhi, llo, wlhi, wllo, bl,
        cat + 1024, cathi + 1024, catlo + 1024, L_DIM, CAT_K);

    // context = tanh(cat @ Wc^T + bc)
    mma_gemm<1><<<dim3(4, 256), 256, GSMEM_BYTES>>>(cathi, catlo, wchi, wclo, bc,
        ctx, (u16*)nullptr, (u16*)nullptr, CAT_K, H_DIM);

    // attention softmax fusion -> fus hi/lo
    fusion_kernel<<<ROWS / 8, 256>>>();

    // xg = fusion @ Wih^T + (bih + bhh)
    mma_gemm<2><<<dim3(16, 256), 256, GSMEM_BYTES>>>(fushi, fuslo, wihhi, wihlo, bsum,
        xg, (u16*)nullptr, (u16*)nullptr, H_DIM, G4);

    // recurrent LSTM
    lstm_kernel<<<NCTA, 256>>>(h0, c0, Whh, out);
}

// round 11
// speedup vs baseline: 1.2528x; 1.2528x over previous
#include <cuda_runtime.h>
#include <cuda_bf16.h>
#include <cstdint>

typedef unsigned long long ull;
typedef unsigned short u16;
typedef unsigned int u32;

// ---------------- Problem constants ----------------
#define A_DIM 512
#define V_DIM 768
#define L_DIM 1024
#define H_DIM 512
#define BB    16
#define SS    2048
#define ROWS  (BB * SS)        // 32768
#define G4    (4 * H_DIM)      // 2048
#define CAT_K 1536

// ---------------- Scratch (device globals; no allocation allowed) ----------------
__device__ float g_cat[(size_t)ROWS * CAT_K];
__device__ float g_ctx[(size_t)ROWS * H_DIM];
__device__ float g_xg [(size_t)ROWS * G4];
__device__ float g_bsum[G4];
__device__ unsigned int g_ctr;

// double-buffered recurrent h, pre-split bf16 hi/lo, plain [b][k] layout
__device__ __align__(16) u16 g_h2hi[2 * BB * H_DIM];
__device__ __align__(16) u16 g_h2lo[2 * BB * H_DIM];

__device__ __align__(16) u16 g_ahi[(size_t)ROWS * A_DIM],  g_alo[(size_t)ROWS * A_DIM];
__device__ __align__(16) u16 g_vhi[(size_t)ROWS * V_DIM],  g_vlo[(size_t)ROWS * V_DIM];
__device__ __align__(16) u16 g_lhi[(size_t)ROWS * L_DIM],  g_llo[(size_t)ROWS * L_DIM];
__device__ __align__(16) u16 g_cathi[(size_t)ROWS * CAT_K], g_catlo[(size_t)ROWS * CAT_K];
__device__ __align__(16) u16 g_fushi[(size_t)ROWS * H_DIM], g_fuslo[(size_t)ROWS * H_DIM];
__device__ __align__(16) u16 g_wahi[H_DIM * A_DIM],  g_walo[H_DIM * A_DIM];
__device__ __align__(16) u16 g_wvhi[H_DIM * V_DIM],  g_wvlo[H_DIM * V_DIM];
__device__ __align__(16) u16 g_wlhi[H_DIM * L_DIM],  g_wllo[H_DIM * L_DIM];
__device__ __align__(16) u16 g_wchi[H_DIM * CAT_K],  g_wclo[H_DIM * CAT_K];
__device__ __align__(16) u16 g_wihhi[G4 * H_DIM],    g_wihlo[G4 * H_DIM];

// ---------------- helpers ----------------
__device__ __forceinline__ float sigmf(float x) { return 1.0f / (1.0f + __expf(-x)); }

__device__ __forceinline__ u32 smem_u32(const void* p) {
    u32 a;
    asm("{ .reg .u64 t; cvta.to.shared.u64 t, %1; cvt.u32.u64 %0, t; }" : "=r"(a) : "l"(p));
    return a;
}

#define SWZ128(x) ((x) ^ (((x) >> 3) & 0x70))

__device__ __forceinline__ void ldsm4(u32& r0, u32& r1, u32& r2, u32& r3, u32 addr) {
    asm volatile("ldmatrix.sync.aligned.m8n8.x4.shared.b16 {%0,%1,%2,%3}, [%4];"
        : "=r"(r0), "=r"(r1), "=r"(r2), "=r"(r3) : "r"(addr));
}
__device__ __forceinline__ void mma16816(float* c, const u32* a, u32 b0, u32 b1) {
    asm volatile("mma.sync.aligned.m16n8k16.row.col.f32.bf16.bf16.f32 "
        "{%0,%1,%2,%3}, {%4,%5,%6,%7}, {%8,%9}, {%0,%1,%2,%3};"
        : "+f"(c[0]), "+f"(c[1]), "+f"(c[2]), "+f"(c[3])
        : "r"(a[0]), "r"(a[1]), "r"(a[2]), "r"(a[3]), "r"(b0), "r"(b1));
}
__device__ __forceinline__ void cp16(u32 saddr, const void* g) {
    asm volatile("cp.async.cg.shared.global [%0], [%1], 16;" :: "r"(saddr), "l"(g));
}
__device__ __forceinline__ u32 ldcg32(const u32* p) {
    u32 v; asm volatile("ld.global.cg.u32 %0, [%1];" : "=r"(v) : "l"(p)); return v;
}
__device__ __forceinline__ u16 bf_hi(float x) {
    __nv_bfloat16 h = __float2bfloat16(x); return *(u16*)&h;
}
__device__ __forceinline__ u16 bf_lo(float x) {
    __nv_bfloat16 h = __float2bfloat16(x);
    float r = x - __bfloat162float(h);
    __nv_bfloat16 l = __float2bfloat16(r);
    return *(u16*)&l;
}

// ---------------- Init: biases, counter, pre-split h0 into slot 0 ----------------
__global__ void init_kernel(const float* __restrict__ bih, const float* __restrict__ bhh,
                            const float* __restrict__ h0) {
    int i = blockIdx.x * blockDim.x + threadIdx.x;
    if (i < G4) g_bsum[i] = bih[i] + bhh[i];
    if (i == 0) g_ctr = 0u;
    if (i < BB * H_DIM) {
        float x = h0[i];
        g_h2hi[i] = bf_hi(x);
        g_h2lo[i] = bf_lo(x);
    }
}

// ---------------- fp32 -> bf16 hi/lo splits (fused, vectorized) ----------------
__device__ __forceinline__ void split4(const float* __restrict__ s, u16* __restrict__ hi,
                                       u16* __restrict__ lo, size_t i) {
    float4 x = ((const float4*)s)[i];
    float xs[4] = { x.x, x.y, x.z, x.w };
    u32 hp[2], lp[2];
#pragma unroll
    for (int q = 0; q < 2; q++) {
        u16 h0 = bf_hi(xs[2 * q]), h1 = bf_hi(xs[2 * q + 1]);
        u16 l0 = bf_lo(xs[2 * q]), l1 = bf_lo(xs[2 * q + 1]);
        hp[q] = (u32)h0 | ((u32)h1 << 16);
        lp[q] = (u32)l0 | ((u32)l1 << 16);
    }
    ((uint2*)hi)[i] = make_uint2(hp[0], hp[1]);
    ((uint2*)lo)[i] = make_uint2(lp[0], lp[1]);
}

__global__ void split_in_kernel(const float* __restrict__ a, const float* __restrict__ v,
                                const float* __restrict__ l) {
    const size_t i = (size_t)blockIdx.x * blockDim.x + threadIdx.x;
    const int seg = blockIdx.y;
    if (seg == 0) { if (i < (size_t)ROWS * A_DIM / 4) split4(a, g_ahi, g_alo, i); }
    else if (seg == 1) { if (i < (size_t)ROWS * V_DIM / 4) split4(v, g_vhi, g_vlo, i); }
    else { split4(l, g_lhi, g_llo, i); }
}

__global__ void split_w_kernel(const float* __restrict__ wa, const float* __restrict__ wv,
                               const float* __restrict__ wl, const float* __restrict__ wc,
                               const float* __restrict__ wih) {
    const size_t i = (size_t)blockIdx.x * blockDim.x + threadIdx.x;
    const int seg = blockIdx.y;
    if (seg == 0)      { if (i < (size_t)H_DIM * A_DIM / 4) split4(wa, g_wahi, g_walo, i); }
    else if (seg == 1) { if (i < (size_t)H_DIM * V_DIM / 4) split4(wv, g_wvhi, g_wvlo, i); }
    else if (seg == 2) { if (i < (size_t)H_DIM * L_DIM / 4) split4(wl, g_wlhi, g_wllo, i); }
    else if (seg == 3) { if (i < (size_t)H_DIM * CAT_K / 4) split4(wc, g_wchi, g_wclo, i); }
    else               { split4(wih, g_wihhi, g_wihlo, i); }
}

// ---------------- merged-pass pipelined mma.sync GEMM (unchanged from R9) ----------------
#define STAGES 3
#define TILE_B 16384
#define STG_BYTES (4 * TILE_B)
#define GSMEM_BYTES (STAGES * STG_BYTES)

template<int MODE>
__global__ __launch_bounds__(256, 1)
void mma_gemm(const u16* __restrict__ Xhi, const u16* __restrict__ Xlo,
              const u16* __restrict__ Whi, const u16* __restrict__ Wlo,
              const float* __restrict__ bias, float* __restrict__ Cf,
              u16* __restrict__ Chi, u16* __restrict__ Clo,
              int K, int ldc)
{
    extern __shared__ __align__(16) char smem[];
    const u32 sbase = smem_u32(smem);

    const int tid  = threadIdx.x;
    const int lane = tid & 31;
    const int w    = tid >> 5;
    const int wm   = w & 3;
    const int wn   = w >> 2;
    const int m0 = blockIdx.y * 128;
    const int n0 = blockIdx.x * 128;

    float acc[2][8][4];
#pragma unroll
    for (int i = 0; i < 2; i++)
#pragma unroll
        for (int j = 0; j < 8; j++)
#pragma unroll
            for (int q = 0; q < 4; q++) acc[i][j][q] = 0.f;

    const int a_row = wm * 32 + (lane & 15);
    const int a_kb  = (lane >> 4) * 16;
    const int b_row = wn * 64 + (lane & 7) + ((lane >> 4) << 3);
    const int b_kb  = ((lane >> 3) & 1) * 16;

    const int KP = K / 64;

    auto issue = [&](int ch) {
        if (ch < KP) {
            const int kk = ch;
            const u16* A0 = Xhi + (size_t)m0 * K + kk * 64;
            const u16* A1 = Xlo + (size_t)m0 * K + kk * 64;
            const u16* B0 = Whi + (size_t)n0 * K + kk * 64;
            const u16* B1 = Wlo + (size_t)n0 * K + kk * 64;
            const u32 st = sbase + (ch % STAGES) * STG_BYTES;
#pragma unroll
            for (int i = 0; i < 4; i++) {
                const int id  = tid + 256 * i;
                const int row = id >> 3;
                const int c   = id & 7;
                const u32 off = SWZ128(row * 128 + c * 16);
                const size_t g = (size_t)row * K + c * 8;
                cp16(st + 0 * TILE_B + off, A0 + g);
                cp16(st + 1 * TILE_B + off, A1 + g);
                cp16(st + 2 * TILE_B + off, B0 + g);
                cp16(st + 3 * TILE_B + off, B1 + g);
            }
        }
        asm volatile("cp.async.commit_group;");
    };

    issue(0);
    issue(1);

    for (int ch = 0; ch < KP; ch++) {
        asm volatile("cp.async.wait_group 1;");
        __syncthreads();
        issue(ch + 2);

        const u32 st = sbase + (ch % STAGES) * STG_BYTES;
        const u32 sAh = st, sAl = st + TILE_B, sBh = st + 2 * TILE_B, sBl = st + 3 * TILE_B;

#pragma unroll
        for (int ks = 0; ks < 4; ks++) {
            const int kb = ks * 32;
            u32 ah[2][4], al[2][4];
#pragma unroll
            for (int mt = 0; mt < 2; mt++) {
                const u32 ao = SWZ128((a_row + mt * 16) * 128 + a_kb + kb);
                ldsm4(ah[mt][0], ah[mt][1], ah[mt][2], ah[mt][3], sAh + ao);
                ldsm4(al[mt][0], al[mt][1], al[mt][2], al[mt][3], sAl + ao);
            }
#pragma unroll
            for (int nt = 0; nt < 4; nt++) {
                const u32 bo = SWZ128((b_row + nt * 16) * 128 + b_kb + kb);
                u32 bh0, bh1, bh2, bh3, bl0, bl1, bl2, bl3;
                ldsm4(bh0, bh1, bh2, bh3, sBh + bo);
                ldsm4(bl0, bl1, bl2, bl3, sBl + bo);
#pragma unroll
                for (int mt = 0; mt < 2; mt++) {
                    mma16816(acc[mt][2 * nt],     ah[mt], bh0, bh1);
                    mma16816(acc[mt][2 * nt + 1], ah[mt], bh2, bh3);
                    mma16816(acc[mt][2 * nt],     ah[mt], bl0, bl1);
                    mma16816(acc[mt][2 * nt + 1], ah[mt], bl2, bl3);
                    mma16816(acc[mt][2 * nt],     al[mt], bh0, bh1);
                    mma16816(acc[mt][2 * nt + 1], al[mt], bh2, bh3);
                }
            }
        }
    }

    const int mb = m0 + wm * 32 + (lane >> 2);
    const int nb = n0 + wn * 64 + (lane & 3) * 2;
#pragma unroll
    for (int mt = 0; mt < 2; mt++) {
#pragma unroll
        for (int nt = 0; nt < 8; nt++) {
            const int n = nb + nt * 8;
            const float b0 = bias[n], b1 = bias[n + 1];
#pragma unroll
            for (int h = 0; h < 2; h++) {
                const int m = mb + mt * 16 + h * 8;
                float v0 = acc[mt][nt][2 * h]     + b0;
                float v1 = acc[mt][nt][2 * h + 1] + b1;
                if (MODE == 1) { v0 = tanhf(v0); v1 = tanhf(v1); }
                *(float2*)&Cf[(size_t)m * ldc + n] = make_float2(v0, v1);
                if (MODE == 0) {
                    u32 hp = (u32)bf_hi(v0) | ((u32)bf_hi(v1) << 16);
                    u32 lp = (u32)bf_lo(v0) | ((u32)bf_lo(v1) << 16);
                    *(u32*)&Chi[(size_t)m * ldc + n] = hp;
                    *(u32*)&Clo[(size_t)m * ldc + n] = lp;
                }
            }
        }
    }
}

// ---------------- Attention fusion -> bf16 hi/lo fusion ----------------
__global__ __launch_bounds__(256)
void fusion_kernel()
{
    const int warp = threadIdx.x >> 5;
    const int lane = threadIdx.x & 31;
    const int row  = blockIdx.x * 8 + warp;

    const float* crow = g_cat + (size_t)row * CAT_K;
    const float* xrow = g_ctx + (size_t)row * H_DIM;

    float av[16], vv[16], lv[16];
    float sa = 0.f, sv = 0.f, sl = 0.f;
#pragma unroll
    for (int q = 0; q < 16; q++) {
        const int k = lane + 32 * q;
        const float c = xrow[k];
        av[q] = crow[k];
        vv[q] = crow[512 + k];
        lv[q] = crow[1024 + k];
        sa = fmaf(av[q], c, sa);
        sv = fmaf(vv[q], c, sv);
        sl = fmaf(lv[q], c, sl);
    }
#pragma unroll
    for (int m = 16; m >= 1; m >>= 1) {
        sa += __shfl_xor_sync(0xffffffffu, sa, m);
        sv += __shfl_xor_sync(0xffffffffu, sv, m);
        sl += __shfl_xor_sync(0xffffffffu, sl, m);
    }
    const float mx = fmaxf(sa, fmaxf(sv, sl));
    const float ea = __expf(sa - mx);
    const float ev = __expf(sv - mx);
    const float el = __expf(sl - mx);
    const float inv = 1.0f / (ea + ev + el);
    const float wa = ea * inv, wv = ev * inv, wl = el * inv;

    u16* fh = g_fushi + (size_t)row * H_DIM;
    u16* fl = g_fuslo + (size_t)row * H_DIM;
#pragma unroll
    for (int q = 0; q < 16; q++) {
        const int k = lane + 32 * q;
        const float v = wa * av[q] + wv * vv[q] + wl * lv[q];
        fh[k] = bf_hi(v);
        fl[k] = bf_lo(v);
    }
}

// ---------------- Persistent LSTM: tensor-core recurrent matvec ----------------
// 128 CTAs x 256 threads. CTA c owns gate rows {g*512 + 4c + j}, i.e. h-cols [4c,4c+4).
// Whh bf16 hi/lo B-fragments register-resident (K split across 8 warps, 64 each).
// h published as bf16 hi/lo; A-fragments loaded straight from L2 (ld.global.cg).
#define NCTA 128
#define OFF_R ((size_t)BB * SS * H_DIM)

__global__ __launch_bounds__(256, 1)
void lstm_kernel(const float* __restrict__ c0, const float* __restrict__ Whh,
                 float* __restrict__ out)
{
    __shared__ __align__(16) float s_red[8 * 32 * 8];     // 8KB warp partials
    __shared__ float s_gates[4][4][BB];                   // 1KB
    __shared__ __align__(16) u16 s_wtile[16 * 512];       // 16KB weight staging

    const int tid  = threadIdx.x;
    const int w    = tid >> 5;
    const int lane = tid & 31;
    const int c    = blockIdx.x;

    // ldmatrix B addressing (16 rows x 1024B tile)
    const int b_row = (lane & 7) + ((lane >> 4) << 3);
    const int b_kb  = ((lane >> 3) & 1) * 16;
    const u32 wb = smem_u32(s_wtile);

    // ---- one-time: stage Whh rows, capture B-fragments in registers ----
    u32 bfrag[2][4][4];   // [term hi/lo][ks][reg]
#pragma unroll
    for (int term = 0; term < 2; term++) {
        for (int e = tid; e < 16 * 512; e += 256) {
            const int nloc = e >> 9, k = e & 511;
            const int grow = (nloc >> 2) * H_DIM + 4 * c + (nloc & 3);
            const float wv = Whh[(size_t)grow * H_DIM + k];
            s_wtile[e] = term ? bf_lo(wv) : bf_hi(wv);
        }
        __syncthreads();
#pragma unroll
        for (int ks = 0; ks < 4; ks++) {
            const u32 addr = wb + b_row * 1024 + (64 * w + 16 * ks) * 2 + b_kb;
            ldsm4(bfrag[term][ks][0], bfrag[term][ks][1],
                  bfrag[term][ks][2], bfrag[term][ks][3], addr);
        }
        __syncthreads();
    }

    // combine-thread state
    const int jn = tid >> 4;   // 0..3 (tid<64)
    const int b  = tid & 15;
    float c_val = 0.f;
    if (tid < 64) c_val = c0[b * H_DIM + 4 * c + jn];

    // A-fragment base u32 index (per warp K-range 64w)
    const int abase = (lane >> 2) * 256 + (w * 64 >> 1) + (lane & 3);

    for (int t = 0; t < SS; t++) {
        // prefetch xg (independent of recurrence)
        float xv0 = 0.f, xv1 = 0.f, xv2 = 0.f, xv3 = 0.f;
        if (tid < 64) {
            const float* xr = g_xg + ((size_t)(b * SS + t)) * G4 + 4 * c + jn;
            xv0 = xr[0 * H_DIM];
            xv1 = xr[1 * H_DIM];
            xv2 = xr[2 * H_DIM];
            xv3 = xr[3 * H_DIM];
        }

        // wait for h_{t-1}
        if (t > 0) {
            if (tid == 0) {
                const unsigned target = (unsigned)NCTA * (unsigned)t;
                while (*(volatile unsigned*)&g_ctr < target) {}
                __threadfence();
            }
            __syncthreads();
        }

        // A-fragments from L2 (bypass L1)
        const u32* Hh = (const u32*)g_h2hi + (t & 1) * (BB * H_DIM / 2);
        const u32* Hl = (const u32*)g_h2lo + (t & 1) * (BB * H_DIM / 2);
        u32 ahi[4][4], alo[4][4];
#pragma unroll
        for (int ks = 0; ks < 4; ks++) {
            const int idx = abase + ks * 8;
            ahi[ks][0] = ldcg32(Hh + idx);
            ahi[ks][1] = ldcg32(Hh + idx + 2048);
            ahi[ks][2] = ldcg32(Hh + idx + 4);
            ahi[ks][3] = ldcg32(Hh + idx + 2052);
            alo[ks][0] = ldcg32(Hl + idx);
            alo[ks][1] = ldcg32(Hl + idx + 2048);
            alo[ks][2] = ldcg32(Hl + idx + 4);
            alo[ks][3] = ldcg32(Hl + idx + 2052);
        }

        float acc[2][4];
#pragma unroll
        for (int nt = 0; nt < 2; nt++)
#pragma unroll
            for (int q = 0; q < 4; q++) acc[nt][q] = 0.f;

#pragma unroll
        for (int ks = 0; ks < 4; ks++) {
#pragma unroll
            for (int nt = 0; nt < 2; nt++) {
                mma16816(acc[nt], ahi[ks], bfrag[0][ks][2 * nt], bfrag[0][ks][2 * nt + 1]);
                mma16816(acc[nt], ahi[ks], bfrag[1][ks][2 * nt], bfrag[1][ks][2 * nt + 1]);
                mma16816(acc[nt], alo[ks], bfrag[0][ks][2 * nt], bfrag[0][ks][2 * nt + 1]);
            }
        }

        // cross-warp reduction via smem
        *(float4*)&s_red[(w * 32 + lane) * 8]     = make_float4(acc[0][0], acc[0][1], acc[0][2], acc[0][3]);
        *(float4*)&s_red[(w * 32 + lane) * 8 + 4] = make_float4(acc[1][0], acc[1][1], acc[1][2], acc[1][3]);
        __syncthreads();
        {
            const int m = tid >> 4, nloc = tid & 15;
            const int nt = nloc >> 3;
            const int rl = ((m & 7) << 2) | ((nloc & 7) >> 1);
            const int q  = ((m >> 3) << 1) | (nloc & 1);
            float v = 0.f;
#pragma unroll
            for (int w8 = 0; w8 < 8; w8++)
                v += s_red[(w8 * 32 + rl) * 8 + nt * 4 + q];
            s_gates[nloc >> 2][nloc & 3][m] = v;
        }
        __syncthreads();

        // combine + state update + publish h (bf16 hi/lo)
        float h = 0.f;
        int col = 0;
        if (tid < 64) {
            const float gi = s_gates[0][jn][b] + xv0;
            const float gf = s_gates[1][jn][b] + xv1;
            const float gg = s_gates[2][jn][b] + xv2;
            const float go = s_gates[3][jn][b] + xv3;
            const float iv = sigmf(gi);
            const float fv = sigmf(gf);
            const float gv = tanhf(gg);
            const float ov = sigmf(go);
            c_val = fv * c_val + iv * gv;
            h = ov * tanhf(c_val);
            col = 4 * c + jn;
            const int ws = ((t + 1) & 1) * (BB * H_DIM) + b * H_DIM + col;
            g_h2hi[ws] = bf_hi(h);
            g_h2lo[ws] = bf_lo(h);
        }
        __syncthreads();
        if (tid == 0) {
            __threadfence();
            atomicAdd(&g_ctr, 1u);
        }

        // out writes OFF the critical path (after signal)
        if (tid < 64) {
            out[((size_t)(b * SS + t)) * H_DIM + col] = h;
            if (t == SS - 1) {
                out[OFF_R + b * H_DIM + col]              = h;
                out[OFF_R + BB * H_DIM + b * H_DIM + col] = c_val;
            }
        }
    }
}

// ---------------- Launch ----------------
extern "C" void kernel_launch(void* const* d_in, const int* in_sizes, int n_in,
                              void* d_out, int out_size)
{
    const float* a_in = (const float*)d_in[0];
    const float* v_in = (const float*)d_in[1];
    const float* l_in = (const float*)d_in[2];
    const float* h0   = (const float*)d_in[3];
    const float* c0   = (const float*)d_in[4];
    const float* Wa   = (const float*)d_in[5];
    const float* ba   = (const float*)d_in[6];
    const float* Wv   = (const float*)d_in[7];
    const float* bv   = (const float*)d_in[8];
    const float* Wl   = (const float*)d_in[9];
    const float* bl   = (const float*)d_in[10];
    const float* Wc   = (const float*)d_in[11];
    const float* bc   = (const float*)d_in[12];
    const float* Wih  = (const float*)d_in[13];
    const float* Whh  = (const float*)d_in[14];
    const float* bih  = (const float*)d_in[15];
    const float* bhh  = (const float*)d_in[16];
    float* out = (float*)d_out;

    float *cat, *ctx, *xg, *bsum;
    cudaGetSymbolAddress((void**)&cat,  g_cat);
    cudaGetSymbolAddress((void**)&ctx,  g_ctx);
    cudaGetSymbolAddress((void**)&xg,   g_xg);
    cudaGetSymbolAddress((void**)&bsum, g_bsum);
    u16 *ahi,*alo,*vhi,*vlo,*lhi,*llo,*cathi,*catlo,*fushi,*fuslo;
    u16 *wahi,*walo,*wvhi,*wvlo,*wlhi,*wllo,*wchi,*wclo,*wihhi,*wihlo;
    cudaGetSymbolAddress((void**)&ahi, g_ahi);   cudaGetSymbolAddress((void**)&alo, g_alo);
    cudaGetSymbolAddress((void**)&vhi, g_vhi);   cudaGetSymbolAddress((void**)&vlo, g_vlo);
    cudaGetSymbolAddress((void**)&lhi, g_lhi);   cudaGetSymbolAddress((void**)&llo, g_llo);
    cudaGetSymbolAddress((void**)&cathi, g_cathi); cudaGetSymbolAddress((void**)&catlo, g_catlo);
    cudaGetSymbolAddress((void**)&fushi, g_fushi); cudaGetSymbolAddress((void**)&fuslo, g_fuslo);
    cudaGetSymbolAddress((void**)&wahi, g_wahi); cudaGetSymbolAddress((void**)&walo, g_walo);
    cudaGetSymbolAddress((void**)&wvhi, g_wvhi); cudaGetSymbolAddress((void**)&wvlo, g_wvlo);
    cudaGetSymbolAddress((void**)&wlhi, g_wlhi); cudaGetSymbolAddress((void**)&wllo, g_wllo);
    cudaGetSymbolAddress((void**)&wchi, g_wchi); cudaGetSymbolAddress((void**)&wclo, g_wclo);
    cudaGetSymbolAddress((void**)&wihhi, g_wihhi); cudaGetSymbolAddress((void**)&wihlo, g_wihlo);

    cudaFuncSetAttribute(mma_gemm<0>, cudaFuncAttributeMaxDynamicSharedMemorySize, GSMEM_BYTES);
    cudaFuncSetAttribute(mma_gemm<1>, cudaFuncAttributeMaxDynamicSharedMemorySize, GSMEM_BYTES);
    cudaFuncSetAttribute(mma_gemm<2>, cudaFuncAttributeMaxDynamicSharedMemorySize, GSMEM_BYTES);

    init_kernel<<<8, 1024>>>(bih, bhh, h0);
    split_in_kernel<<<dim3(32768, 3), 256>>>(a_in, v_in, l_in);
    split_w_kernel<<<dim3(1024, 5), 256>>>(Wa, Wv, Wl, Wc, Wih);

    // projections -> cat fp32 + cat hi/lo (row stride 1536)
    mma_gemm<0><<<dim3(4, 256), 256, GSMEM_BYTES>>>(ahi, alo, wahi, walo, ba,
        cat,        cathi,        catlo,        A_DIM, CAT_K);
    mma_gemm<0><<<dim3(4, 256), 256, GSMEM_BYTES>>>(vhi, vlo, wvhi, wvlo, bv,
        cat + 512,  cathi + 512,  catlo + 512,  V_DIM, CAT_K);
    mma_gemm<0><<<dim3(4, 256), 256, GSMEM_BYTES>>>(lhi, llo, wlhi, wllo, bl,
        cat + 1024, cathi + 1024, catlo + 1024, L_DIM, CAT_K);

    // context = tanh(cat @ Wc^T + bc)
    mma_gemm<1><<<dim3(4, 256), 256, GSMEM_BYTES>>>(cathi, catlo, wchi, wclo, bc,
        ctx, (u16*)nullptr, (u16*)nullptr, CAT_K, H_DIM);

    // attention softmax fusion -> fus hi/lo
    fusion_kernel<<<ROWS / 8, 256>>>();

    // xg = fusion @ Wih^T + (bih + bhh)
    mma_gemm<2><<<dim3(16, 256), 256, GSMEM_BYTES>>>(fushi, fuslo, wihhi, wihlo, bsum,
        xg, (u16*)nullptr, (u16*)nullptr, H_DIM, G4);

    // recurrent LSTM (tensor-core)
    lstm_kernel<<<NCTA, 256>>>(c0, Whh, out);
}